// round 7
// baseline (speedup 1.0000x reference)
#include <cuda_runtime.h>
#include <cuda_bf16.h>
#include <math.h>

#define N_LAYERS 4
#define N_EMBD   1024
#define D_INNER  2048
#define D_STATE  16
#define DT_RANK  64
#define D_CONV   4
#define VOCAB    50257
#define SEQLEN   2048
#define XPROJ_N  (DT_RANK + 2 * D_STATE)   // 96

// ---------------- scratch (allocation-free: __device__ globals) ----------------
__device__ __align__(16) float g_x    [SEQLEN * N_EMBD];        // residual stream
__device__ __align__(16) float g_h    [SEQLEN * N_EMBD];        // rmsnorm output
__device__ __align__(16) float g_xr   [SEQLEN * 2 * D_INNER];   // in_proj output [xc | res]
__device__ __align__(16) float g_xc   [SEQLEN * D_INNER];       // conv+silu output (u)
__device__ __align__(16) float g_xdbl [SEQLEN * XPROJ_N];       // [dt | B | C]
__device__ __align__(16) float g_delta[SEQLEN * D_INNER];
__device__ __align__(16) float g_y    [SEQLEN * D_INNER];

// ---------------- small helpers ----------------
// silu is elementwise (non-compounding) -> fast exp is safe vs 1e-3 threshold
__device__ __forceinline__ float siluf(float x)     { return x * (1.f / (1.f + __expf(-x))); }
// softplus feeds delta -> scan recurrence; keep precise path
__device__ __forceinline__ float softplusf(float x) { return (x > 20.f) ? x : log1pf(expf(x)); }

// ---------------- embedding ----------------
__global__ void embed_kernel(const int* __restrict__ tokens,
                             const float* __restrict__ embW,
                             float* __restrict__ x) {
    int idx = blockIdx.x * blockDim.x + threadIdx.x;   // over SEQLEN*N_EMBD
    int t = idx >> 10;        // / N_EMBD
    int e = idx & 1023;
    x[idx] = embW[(size_t)tokens[t] * N_EMBD + e];
}

// ---------------- rmsnorm (one block per row of 1024) ----------------
__global__ void rmsnorm_kernel(const float* __restrict__ x,
                               const float* __restrict__ w,
                               const float* __restrict__ b,
                               float* __restrict__ out) {
    int row = blockIdx.x;
    const float* xr = x + (size_t)row * N_EMBD;
    float s = 0.f;
    for (int i = threadIdx.x; i < N_EMBD; i += blockDim.x) {
        float v = xr[i];
        s += v * v;
    }
    __shared__ float red[32];
    int lane = threadIdx.x & 31, wid = threadIdx.x >> 5;
    #pragma unroll
    for (int o = 16; o; o >>= 1) s += __shfl_xor_sync(0xffffffffu, s, o);
    if (lane == 0) red[wid] = s;
    __syncthreads();
    if (wid == 0) {
        s = (lane < (blockDim.x >> 5)) ? red[lane] : 0.f;
        #pragma unroll
        for (int o = 16; o; o >>= 1) s += __shfl_xor_sync(0xffffffffu, s, o);
        if (lane == 0) red[0] = s;
    }
    __syncthreads();
    float inv = rsqrtf(red[0] * (1.f / N_EMBD) + 1e-6f);
    for (int i = threadIdx.x; i < N_EMBD; i += blockDim.x)
        out[(size_t)row * N_EMBD + i] = xr[i] * inv * w[i] + b[i];
}

// ---------------- depthwise causal conv (k=4) + silu ----------------
__global__ void conv_silu_kernel(const float* __restrict__ xr,   // [L, 2*D_INNER], xc part
                                 const float* __restrict__ cw,   // [D_INNER, 4]
                                 const float* __restrict__ cb,   // [D_INNER]
                                 float* __restrict__ xc) {       // [L, D_INNER]
    int idx = blockIdx.x * blockDim.x + threadIdx.x;   // over L*D_INNER
    int d = idx & (D_INNER - 1);
    int t = idx >> 11;   // / D_INNER
    const float* w = cw + d * D_CONV;
    float acc = cb[d];
    #pragma unroll
    for (int k = 0; k < D_CONV; ++k) {
        int tt = t - (D_CONV - 1) + k;
        if (tt >= 0) acc += w[k] * xr[(size_t)tt * (2 * D_INNER) + d];
    }
    xc[idx] = siluf(acc);
}

// ---------------- generic tiled SGEMM: C = act(A[M,K] * W[N,K]^T + bias) (+ add) ----------------
// ACT: 0 = none, 1 = softplus
template<bool BIAS, bool ADD, int ACT>
__global__ __launch_bounds__(256)
void sgemm_bt(const float* __restrict__ A, int lda,
              const float* __restrict__ W,            // [N,K] row-major
              const float* __restrict__ bias,
              const float* __restrict__ Cadd, int ldadd,
              float* __restrict__ C, int ldc,
              int M, int N, int K) {
    constexpr int BM = 128, BN = 128, BK = 8, TM = 8, TN = 8;
    __shared__ float As[BK][BM];
    __shared__ float Bs[BK][BN];

    int tid = threadIdx.x;
    int row0 = blockIdx.y * BM;
    int col0 = blockIdx.x * BN;

    int lrow = tid >> 1;            // 0..127
    int lcol = (tid & 1) * 4;       // 0 or 4

    int ty = tid >> 4;              // 0..15
    int tx = tid & 15;              // 0..15

    float acc[TM][TN];
    #pragma unroll
    for (int i = 0; i < TM; ++i)
        #pragma unroll
        for (int j = 0; j < TN; ++j) acc[i][j] = 0.f;

    for (int k0 = 0; k0 < K; k0 += BK) {
        // load A tile (M is always a multiple of BM here)
        float4 av = *(const float4*)(A + (size_t)(row0 + lrow) * lda + k0 + lcol);
        As[lcol + 0][lrow] = av.x;
        As[lcol + 1][lrow] = av.y;
        As[lcol + 2][lrow] = av.z;
        As[lcol + 3][lrow] = av.w;
        // load W tile (guard N)
        float4 bv = make_float4(0.f, 0.f, 0.f, 0.f);
        if (col0 + lrow < N)
            bv = *(const float4*)(W + (size_t)(col0 + lrow) * K + k0 + lcol);
        Bs[lcol + 0][lrow] = bv.x;
        Bs[lcol + 1][lrow] = bv.y;
        Bs[lcol + 2][lrow] = bv.z;
        Bs[lcol + 3][lrow] = bv.w;
        __syncthreads();

        #pragma unroll
        for (int kk = 0; kk < BK; ++kk) {
            float a[TM], bf[TN];
            #pragma unroll
            for (int i = 0; i < TM; ++i) a[i] = As[kk][ty * TM + i];
            #pragma unroll
            for (int j = 0; j < TN; ++j) bf[j] = Bs[kk][tx * TN + j];
            #pragma unroll
            for (int i = 0; i < TM; ++i)
                #pragma unroll
                for (int j = 0; j < TN; ++j)
                    acc[i][j] = fmaf(a[i], bf[j], acc[i][j]);
        }
        __syncthreads();
    }

    // epilogue: cache bias per column once
    float bcol[TN];
    if (BIAS) {
        #pragma unroll
        for (int j = 0; j < TN; ++j) {
            int c = col0 + tx * TN + j;
            bcol[j] = (c < N) ? bias[c] : 0.f;
        }
    }
    #pragma unroll
    for (int i = 0; i < TM; ++i) {
        int r = row0 + ty * TM + i;
        #pragma unroll
        for (int j = 0; j < TN; ++j) {
            int c = col0 + tx * TN + j;
            if (c < N) {
                float v = acc[i][j];
                if (BIAS) v += bcol[j];
                if (ACT == 1) v = softplusf(v);
                if (ADD) v += Cadd[(size_t)r * ldadd + c];
                C[(size_t)r * ldc + c] = v;
            }
        }
    }
}

// ---------------- selective scan ----------------
// one thread per (d, n) lane; n = lane%16 so the sum over n is a 16-lane shfl reduction.
// fuses:  y_out[t,d] = (scan_y + u*D[d]) * silu(res[t,d])
__global__ __launch_bounds__(256)
void scan_kernel(const float* __restrict__ u,      // [L, D_INNER]
                 const float* __restrict__ delta,  // [L, D_INNER]
                 const float* __restrict__ Alog,   // [D_INNER, 16]
                 const float* __restrict__ Bm,     // [L, *] at +ldbc stride
                 const float* __restrict__ Cm,
                 int ldbc,
                 const float* __restrict__ Dp,     // [D_INNER]
                 const float* __restrict__ res,    // [L, *] stride ldres
                 int ldres,
                 float* __restrict__ y)            // [L, D_INNER]
{
    int idx = blockIdx.x * blockDim.x + threadIdx.x;   // 0 .. D_INNER*D_STATE-1
    int d = idx >> 4;
    int n = idx & 15;
    float A = -expf(Alog[d * D_STATE + n]);
    float Dd = Dp[d];
    float s = 0.f;

    // unroll 4: batches the 4 independent load streams ahead of the serial
    // recurrence chain (raises MLP while the expf+fma chain drains)
    #pragma unroll 4
    for (int t = 0; t < SEQLEN; ++t) {
        float dlt = delta[(size_t)t * D_INNER + d];
        float uu  = u[(size_t)t * D_INNER + d];
        float Bt  = Bm[(size_t)t * ldbc + n];
        float Ct  = Cm[(size_t)t * ldbc + n];
        s = expf(dlt * A) * s + dlt * Bt * uu;
        float yv = s * Ct;
        yv += __shfl_xor_sync(0xffffffffu, yv, 1);
        yv += __shfl_xor_sync(0xffffffffu, yv, 2);
        yv += __shfl_xor_sync(0xffffffffu, yv, 4);
        yv += __shfl_xor_sync(0xffffffffu, yv, 8);
        if (n == 0) {
            float r = res[(size_t)t * ldres + d];
            y[(size_t)t * D_INNER + d] = (yv + uu * Dd) * siluf(r);
        }
    }
}

// ---------------- host orchestration ----------------
extern "C" void kernel_launch(void* const* d_in, const int* in_sizes, int n_in,
                              void* d_out, int out_size) {
    const int*   tokens   = (const int*)  d_in[0];
    const float* emb_W    = (const float*)d_in[1];   // [VOCAB, N_EMBD]
    const float* in_proj  = (const float*)d_in[2];   // [4, 2*D_INNER, N_EMBD]
    const float* conv_W   = (const float*)d_in[3];   // [4, D_INNER, 1, 4]
    const float* conv_b   = (const float*)d_in[4];   // [4, D_INNER]
    const float* xproj_W  = (const float*)d_in[5];   // [4, 96, D_INNER]
    const float* dt_W     = (const float*)d_in[6];   // [4, D_INNER, 64]
    const float* dt_b     = (const float*)d_in[7];   // [4, D_INNER]
    const float* A_log    = (const float*)d_in[8];   // [4, D_INNER, 16]
    const float* Dp       = (const float*)d_in[9];   // [4, D_INNER]
    const float* out_W    = (const float*)d_in[10];  // [4, N_EMBD, D_INNER]
    const float* rms_w    = (const float*)d_in[11];  // [4, N_EMBD]
    const float* rms_b    = (const float*)d_in[12];
    const float* normf_w  = (const float*)d_in[13];  // [N_EMBD]
    const float* normf_b  = (const float*)d_in[14];
    float* out = (float*)d_out;                      // [SEQLEN, VOCAB]

    float *x, *h, *xr, *xc, *xdbl, *dlt, *y;
    cudaGetSymbolAddress((void**)&x,    g_x);
    cudaGetSymbolAddress((void**)&h,    g_h);
    cudaGetSymbolAddress((void**)&xr,   g_xr);
    cudaGetSymbolAddress((void**)&xc,   g_xc);
    cudaGetSymbolAddress((void**)&xdbl, g_xdbl);
    cudaGetSymbolAddress((void**)&dlt,  g_delta);
    cudaGetSymbolAddress((void**)&y,    g_y);

    // embedding
    embed_kernel<<<(SEQLEN * N_EMBD) / 256, 256>>>(tokens, emb_W, x);

    for (int i = 0; i < N_LAYERS; ++i) {
        // h = rmsnorm(x)
        rmsnorm_kernel<<<SEQLEN, 256>>>(x, rms_w + i * N_EMBD, rms_b + i * N_EMBD, h);

        // xr = h @ in_proj[i]^T     [2048, 4096]
        sgemm_bt<false, false, 0><<<dim3(2 * D_INNER / 128, SEQLEN / 128), 256>>>(
            h, N_EMBD, in_proj + (size_t)i * 2 * D_INNER * N_EMBD,
            nullptr, nullptr, 0, xr, 2 * D_INNER, SEQLEN, 2 * D_INNER, N_EMBD);

        // xc = silu(causal_conv(xr[:, :D_INNER]))
        conv_silu_kernel<<<(SEQLEN * D_INNER) / 256, 256>>>(
            xr, conv_W + (size_t)i * D_INNER * D_CONV, conv_b + (size_t)i * D_INNER, xc);

        // x_dbl = xc @ xproj[i]^T   [2048, 96]
        sgemm_bt<false, false, 0><<<dim3(1, SEQLEN / 128), 256>>>(
            xc, D_INNER, xproj_W + (size_t)i * XPROJ_N * D_INNER,
            nullptr, nullptr, 0, xdbl, XPROJ_N, SEQLEN, XPROJ_N, D_INNER);

        // delta = softplus(x_dbl[:, :64] @ dt_W[i]^T + dt_b[i])   [2048, 2048]
        sgemm_bt<true, false, 1><<<dim3(D_INNER / 128, SEQLEN / 128), 256>>>(
            xdbl, XPROJ_N, dt_W + (size_t)i * D_INNER * DT_RANK,
            dt_b + (size_t)i * D_INNER, nullptr, 0, dlt, D_INNER,
            SEQLEN, D_INNER, DT_RANK);

        // selective scan (fused: + u*D, * silu(res))
        scan_kernel<<<(D_INNER * D_STATE) / 256, 256>>>(
            xc, dlt, A_log + (size_t)i * D_INNER * D_STATE,
            xdbl + DT_RANK, xdbl + DT_RANK + D_STATE, XPROJ_N,
            Dp + (size_t)i * D_INNER, xr + D_INNER, 2 * D_INNER, y);

        // x = x + y @ out_W[i]^T    [2048, 1024]
        sgemm_bt<false, true, 0><<<dim3(N_EMBD / 128, SEQLEN / 128), 256>>>(
            y, D_INNER, out_W + (size_t)i * N_EMBD * D_INNER,
            nullptr, x, N_EMBD, x, N_EMBD, SEQLEN, N_EMBD, D_INNER);
    }

    // final norm + tied LM head
    rmsnorm_kernel<<<SEQLEN, 256>>>(x, normf_w, normf_b, h);
    sgemm_bt<false, false, 0><<<dim3((VOCAB + 127) / 128, SEQLEN / 128), 256>>>(
        h, N_EMBD, emb_W, nullptr, nullptr, 0, out, VOCAB, SEQLEN, VOCAB, N_EMBD);
}

// round 11
// speedup vs baseline: 1.6537x; 1.6537x over previous
#include <cuda_runtime.h>
#include <cuda_bf16.h>
#include <math.h>
#include <stdint.h>

#define N_LAYERS 4
#define N_EMBD   1024
#define D_INNER  2048
#define D_STATE  16
#define DT_RANK  64
#define D_CONV   4
#define VOCAB    50257
#define SEQLEN   2048
#define XPROJ_N  (DT_RANK + 2 * D_STATE)   // 96

// ================= scratch (allocation-free: __device__ globals) =================
__device__ __align__(16) float g_x    [SEQLEN * N_EMBD];        // residual stream
__device__ __align__(16) float g_h    [SEQLEN * N_EMBD];        // rmsnorm output
__device__ __align__(16) float g_xr   [SEQLEN * 2 * D_INNER];   // in_proj out [xc | res]
__device__ __align__(16) float g_xc   [SEQLEN * D_INNER];       // conv+silu (u)
__device__ __align__(16) float g_xdbl [SEQLEN * XPROJ_N];       // [dt | B | C]
__device__ __align__(16) float g_delta[SEQLEN * D_INNER];
__device__ __align__(16) float g_y    [SEQLEN * D_INNER];

// ================= helpers =================
__device__ __forceinline__ float siluf(float x)     { return x * (1.f / (1.f + __expf(-x))); }
__device__ __forceinline__ float softplusf(float x) { return (x > 20.f) ? x : log1pf(expf(x)); }

__device__ __forceinline__ uint32_t smem_u32(const void* p) {
    uint32_t a;
    asm("{ .reg .u64 t; cvta.to.shared.u64 t, %1; cvt.u32.u64 %0, t; }" : "=r"(a) : "l"(p));
    return a;
}

// pack two fp32 (already bf16-representable) into a bf16x2 register (low = first)
__device__ __forceinline__ uint32_t pk(float a, float b) {
    __nv_bfloat162 t = __floats2bfloat162_rn(a, b);
    return *reinterpret_cast<uint32_t*>(&t);
}

// split 8 fp32 into bf16 hi (uint4) and bf16 lo (uint4)
__device__ __forceinline__ void split8(const float* f, uint4& H, uint4& L) {
    float hv[8], lv[8];
    #pragma unroll
    for (int i = 0; i < 8; ++i) {
        __nv_bfloat16 h = __float2bfloat16_rn(f[i]);
        hv[i] = __bfloat162float(h);
        lv[i] = f[i] - hv[i];
    }
    H = make_uint4(pk(hv[0], hv[1]), pk(hv[2], hv[3]), pk(hv[4], hv[5]), pk(hv[6], hv[7]));
    L = make_uint4(pk(lv[0], lv[1]), pk(lv[2], lv[3]), pk(lv[4], lv[5]), pk(lv[6], lv[7]));
}

__device__ __forceinline__ void ldmx4(uint32_t addr, uint32_t r[4]) {
    asm volatile("ldmatrix.sync.aligned.m8n8.x4.shared.b16 {%0,%1,%2,%3}, [%4];"
                 : "=r"(r[0]), "=r"(r[1]), "=r"(r[2]), "=r"(r[3]) : "r"(addr));
}

__device__ __forceinline__ void mma16816(float d[4], const uint32_t a[4], const uint32_t b[2]) {
    asm volatile("mma.sync.aligned.m16n8k16.row.col.f32.bf16.bf16.f32 "
                 "{%0,%1,%2,%3}, {%4,%5,%6,%7}, {%8,%9}, {%0,%1,%2,%3};"
                 : "+f"(d[0]), "+f"(d[1]), "+f"(d[2]), "+f"(d[3])
                 : "r"(a[0]), "r"(a[1]), "r"(a[2]), "r"(a[3]), "r"(b[0]), "r"(b[1]));
}

// ================= mma.sync GEMM =================
// C[M,N] = A[M,K] @ W[N,K]^T, fp32 in/out, bf16 hi/lo split (3 HMMAs per frag pair).
// Grid (M/128, ceil(N/128)), 256 threads (8 warps, 2x4, 64x32 warp tiles). K % 16 == 0.
// EPI: 0 = plain fp32; 1 = softplus(v + bias); 2 = v + Cadd (residual)
static constexpr int GEMM_SMEM = 128 * 129 * 4;   // 66048; tiles need 4*6144 = 24576

template<int EPI>
__global__ __launch_bounds__(256)
void mma_gemm(const float* __restrict__ A, int lda,
              const float* __restrict__ W,            // [N,K] row-major
              const float* __restrict__ bias,
              const float* __restrict__ Cadd,
              float* __restrict__ C, int ldc,
              int N, int K)
{
    extern __shared__ char smem[];
    const uint32_t sb = smem_u32(smem);
    const int tid  = threadIdx.x;
    const int wid  = tid >> 5, lane = tid & 31;
    const int wy   = wid >> 2, wx = wid & 3;        // warp grid 2 x 4
    const int row0 = blockIdx.x * 128;
    const int col0 = blockIdx.y * 128;

    // smem tile offsets (rows padded 32B -> 48B: conflict-free ldmatrix, 16B-aligned rows)
    const int OFF_AH = 0, OFF_AL = 6144, OFF_BH = 12288, OFF_BL = 18432;

    // loader mapping: thread -> (row, k-quad)
    const int lr = tid >> 1;            // 0..127
    const int lk = (tid & 1) * 8;       // 0 or 8

    // ldmatrix per-lane address offsets
    // A (16x16 block i): lanes 0-15 -> rows base+(L&15), kbyte 0; lanes 16-31 -> same rows, kbyte 16
    const uint32_t aoff = (uint32_t)((wy * 64 + (lane & 15)) * 48 + (lane >> 4) * 16);
    // B (two 8-row n-blocks per x4): n = wx*32 + (L>>4)*8 + (L&7), kbyte = ((L>>3)&1)*16
    const uint32_t boff = (uint32_t)((wx * 32 + ((lane >> 4) << 3) + (lane & 7)) * 48
                                     + ((lane >> 3) & 1) * 16);
    const uint32_t aAh = sb + OFF_AH + aoff, aAl = sb + OFF_AL + aoff;
    const uint32_t bBh = sb + OFF_BH + boff, bBl = sb + OFF_BL + boff;

    float acc[4][4][4];
    #pragma unroll
    for (int i = 0; i < 4; ++i)
        #pragma unroll
        for (int j = 0; j < 4; ++j)
            #pragma unroll
            for (int r = 0; r < 4; ++r) acc[i][j][r] = 0.f;

    const bool bok = (col0 + lr) < N;
    const float* Arow = A + (size_t)(row0 + lr) * lda + lk;
    const float* Wrow = bok ? (W + (size_t)(col0 + lr) * K + lk) : nullptr;
    char* sA = smem + OFF_AH + lr * 48 + lk * 2;   // +6144 for lo
    char* sB = smem + OFF_BH + lr * 48 + lk * 2;

    for (int k0 = 0; k0 < K; k0 += 16) {
        // ---- load + hi/lo split into smem ----
        {
            float fa[8];
            *(float4*)(fa)     = *(const float4*)(Arow + k0);
            *(float4*)(fa + 4) = *(const float4*)(Arow + k0 + 4);
            uint4 H, L;
            split8(fa, H, L);
            *(uint4*)(sA)        = H;
            *(uint4*)(sA + 6144) = L;

            float fb[8] = {0.f, 0.f, 0.f, 0.f, 0.f, 0.f, 0.f, 0.f};
            if (bok) {
                *(float4*)(fb)     = *(const float4*)(Wrow + k0);
                *(float4*)(fb + 4) = *(const float4*)(Wrow + k0 + 4);
            }
            split8(fb, H, L);
            *(uint4*)(sB)        = H;
            *(uint4*)(sB + 6144) = L;
        }
        __syncthreads();

        // ---- B fragments (4 n-blocks of 8) ----
        uint32_t bh[4][2], bl[4][2];
        {
            uint32_t t[4];
            ldmx4(bBh, t);       bh[0][0] = t[0]; bh[0][1] = t[1]; bh[1][0] = t[2]; bh[1][1] = t[3];
            ldmx4(bBh + 768, t); bh[2][0] = t[0]; bh[2][1] = t[1]; bh[3][0] = t[2]; bh[3][1] = t[3];
            ldmx4(bBl, t);       bl[0][0] = t[0]; bl[0][1] = t[1]; bl[1][0] = t[2]; bl[1][1] = t[3];
            ldmx4(bBl + 768, t); bl[2][0] = t[0]; bl[2][1] = t[1]; bl[3][0] = t[2]; bl[3][1] = t[3];
        }

        // ---- A fragments + MMAs ----
        #pragma unroll
        for (int i = 0; i < 4; ++i) {
            uint32_t ah[4], al[4];
            ldmx4(aAh + i * 768, ah);
            ldmx4(aAl + i * 768, al);
            #pragma unroll
            for (int j = 0; j < 4; ++j) {
                mma16816(acc[i][j], ah, bh[j]);
                mma16816(acc[i][j], ah, bl[j]);
                mma16816(acc[i][j], al, bh[j]);
            }
        }
        __syncthreads();
    }

    // ---- epilogue: stage fp32 through smem (reuse tile space), coalesced stores ----
    float* eb = (float*)smem;
    #pragma unroll
    for (int i = 0; i < 4; ++i) {
        #pragma unroll
        for (int j = 0; j < 4; ++j) {
            int r = wy * 64 + i * 16 + (lane >> 2);
            int c = wx * 32 + j * 8 + (lane & 3) * 2;
            eb[r * 129 + c]           = acc[i][j][0];
            eb[r * 129 + c + 1]       = acc[i][j][1];
            eb[(r + 8) * 129 + c]     = acc[i][j][2];
            eb[(r + 8) * 129 + c + 1] = acc[i][j][3];
        }
    }
    __syncthreads();

    const int cl = tid & 127;
    const int cc = col0 + cl;
    const bool cok = cc < N;
    float bv = 0.f;
    if (EPI == 1 && cok) bv = bias[cc];
    const int rbase = (tid >> 7) * 64;
    for (int kk = 0; kk < 64; ++kk) {
        const int r = row0 + rbase + kk;
        float v = eb[(rbase + kk) * 129 + cl];
        if (cok) {
            if (EPI == 1) v = softplusf(v + bv);
            if (EPI == 2) v += Cadd[(size_t)r * ldc + cc];
            C[(size_t)r * ldc + cc] = v;
        }
    }
}

// ================= embedding =================
__global__ void embed_kernel(const int* __restrict__ tokens,
                             const float* __restrict__ embW,
                             float* __restrict__ x) {
    int idx = blockIdx.x * blockDim.x + threadIdx.x;
    int t = idx >> 10;
    int e = idx & 1023;
    x[idx] = embW[(size_t)tokens[t] * N_EMBD + e];
}

// ================= rmsnorm (fp32 out) =================
__global__ void rmsnorm_kernel(const float* __restrict__ x,
                               const float* __restrict__ w,
                               const float* __restrict__ b,
                               float* __restrict__ out) {
    int row = blockIdx.x;
    const float* xr = x + (size_t)row * N_EMBD;
    float s = 0.f;
    for (int i = threadIdx.x; i < N_EMBD; i += blockDim.x) {
        float v = xr[i];
        s += v * v;
    }
    __shared__ float red[32];
    int lane = threadIdx.x & 31, wid = threadIdx.x >> 5;
    #pragma unroll
    for (int o = 16; o; o >>= 1) s += __shfl_xor_sync(0xffffffffu, s, o);
    if (lane == 0) red[wid] = s;
    __syncthreads();
    if (wid == 0) {
        s = (lane < (blockDim.x >> 5)) ? red[lane] : 0.f;
        #pragma unroll
        for (int o = 16; o; o >>= 1) s += __shfl_xor_sync(0xffffffffu, s, o);
        if (lane == 0) red[0] = s;
    }
    __syncthreads();
    float inv = rsqrtf(red[0] * (1.f / N_EMBD) + 1e-6f);
    for (int i = threadIdx.x; i < N_EMBD; i += blockDim.x)
        out[(size_t)row * N_EMBD + i] = xr[i] * inv * w[i] + b[i];
}

// ================= depthwise causal conv (k=4) + silu =================
__global__ void conv_silu_kernel(const float* __restrict__ xr,
                                 const float* __restrict__ cw,
                                 const float* __restrict__ cb,
                                 float* __restrict__ xc) {
    int idx = blockIdx.x * blockDim.x + threadIdx.x;
    int d = idx & (D_INNER - 1);
    int t = idx >> 11;
    const float* w = cw + d * D_CONV;
    float acc = cb[d];
    #pragma unroll
    for (int k = 0; k < D_CONV; ++k) {
        int tt = t - (D_CONV - 1) + k;
        if (tt >= 0) acc += w[k] * xr[(size_t)tt * (2 * D_INNER) + d];
    }
    xc[idx] = siluf(acc);
}

// ================= selective scan =================
__global__ __launch_bounds__(256)
void scan_kernel(const float* __restrict__ u,
                 const float* __restrict__ delta,
                 const float* __restrict__ Alog,
                 const float* __restrict__ Bm,
                 const float* __restrict__ Cm,
                 int ldbc,
                 const float* __restrict__ Dp,
                 const float* __restrict__ res,
                 int ldres,
                 float* __restrict__ y)
{
    int idx = blockIdx.x * blockDim.x + threadIdx.x;
    int d = idx >> 4;
    int n = idx & 15;
    float A = -expf(Alog[d * D_STATE + n]);
    float Dd = Dp[d];
    float s = 0.f;

    #pragma unroll 4
    for (int t = 0; t < SEQLEN; ++t) {
        float dlt = delta[(size_t)t * D_INNER + d];
        float uu  = u[(size_t)t * D_INNER + d];
        float Bt  = Bm[(size_t)t * ldbc + n];
        float Ct  = Cm[(size_t)t * ldbc + n];
        s = expf(dlt * A) * s + dlt * Bt * uu;
        float yv = s * Ct;
        yv += __shfl_xor_sync(0xffffffffu, yv, 1);
        yv += __shfl_xor_sync(0xffffffffu, yv, 2);
        yv += __shfl_xor_sync(0xffffffffu, yv, 4);
        yv += __shfl_xor_sync(0xffffffffu, yv, 8);
        if (n == 0) {
            float r = res[(size_t)t * ldres + d];
            y[(size_t)t * D_INNER + d] = (yv + uu * Dd) * siluf(r);
        }
    }
}

// ================= host orchestration =================
extern "C" void kernel_launch(void* const* d_in, const int* in_sizes, int n_in,
                              void* d_out, int out_size) {
    const int*   tokens   = (const int*)  d_in[0];
    const float* emb_W    = (const float*)d_in[1];   // [VOCAB, N_EMBD]
    const float* in_proj  = (const float*)d_in[2];   // [4, 2*D_INNER, N_EMBD]
    const float* conv_W   = (const float*)d_in[3];   // [4, D_INNER, 1, 4]
    const float* conv_b   = (const float*)d_in[4];   // [4, D_INNER]
    const float* xproj_W  = (const float*)d_in[5];   // [4, 96, D_INNER]
    const float* dt_W     = (const float*)d_in[6];   // [4, D_INNER, 64]
    const float* dt_b     = (const float*)d_in[7];   // [4, D_INNER]
    const float* A_log    = (const float*)d_in[8];   // [4, D_INNER, 16]
    const float* Dp       = (const float*)d_in[9];   // [4, D_INNER]
    const float* out_W    = (const float*)d_in[10];  // [4, N_EMBD, D_INNER]
    const float* rms_w    = (const float*)d_in[11];
    const float* rms_b    = (const float*)d_in[12];
    const float* normf_w  = (const float*)d_in[13];
    const float* normf_b  = (const float*)d_in[14];
    float* out = (float*)d_out;                      // [SEQLEN, VOCAB]

    // idempotent, non-stream host calls (no static guard: determinism rule)
    cudaFuncSetAttribute(mma_gemm<0>, cudaFuncAttributeMaxDynamicSharedMemorySize, GEMM_SMEM);
    cudaFuncSetAttribute(mma_gemm<1>, cudaFuncAttributeMaxDynamicSharedMemorySize, GEMM_SMEM);
    cudaFuncSetAttribute(mma_gemm<2>, cudaFuncAttributeMaxDynamicSharedMemorySize, GEMM_SMEM);

    float *x, *h, *xr, *xc, *xdbl, *dlt, *y;
    cudaGetSymbolAddress((void**)&x,    g_x);
    cudaGetSymbolAddress((void**)&h,    g_h);
    cudaGetSymbolAddress((void**)&xr,   g_xr);
    cudaGetSymbolAddress((void**)&xc,   g_xc);
    cudaGetSymbolAddress((void**)&xdbl, g_xdbl);
    cudaGetSymbolAddress((void**)&dlt,  g_delta);
    cudaGetSymbolAddress((void**)&y,    g_y);

    embed_kernel<<<(SEQLEN * N_EMBD) / 256, 256>>>(tokens, emb_W, x);

    for (int i = 0; i < N_LAYERS; ++i) {
        // h = rmsnorm(x)
        rmsnorm_kernel<<<SEQLEN, 256>>>(x, rms_w + i * N_EMBD, rms_b + i * N_EMBD, h);

        // xr = h @ in_proj[i]^T   [2048, 4096]
        mma_gemm<0><<<dim3(SEQLEN / 128, 2 * D_INNER / 128), 256, GEMM_SMEM>>>(
            h, N_EMBD, in_proj + (size_t)i * 2 * D_INNER * N_EMBD,
            nullptr, nullptr, xr, 2 * D_INNER, 2 * D_INNER, N_EMBD);

        // xc = silu(causal_conv(xr[:, :D_INNER]))
        conv_silu_kernel<<<(SEQLEN * D_INNER) / 256, 256>>>(
            xr, conv_W + (size_t)i * D_INNER * D_CONV, conv_b + (size_t)i * D_INNER, xc);

        // x_dbl = xc @ xproj[i]^T   [2048, 96]
        mma_gemm<0><<<dim3(SEQLEN / 128, 1), 256, GEMM_SMEM>>>(
            xc, D_INNER, xproj_W + (size_t)i * XPROJ_N * D_INNER,
            nullptr, nullptr, xdbl, XPROJ_N, XPROJ_N, D_INNER);

        // delta = softplus(x_dbl[:, :64] @ dt_W[i]^T + dt_b[i])   [2048, 2048]
        mma_gemm<1><<<dim3(SEQLEN / 128, D_INNER / 128), 256, GEMM_SMEM>>>(
            xdbl, XPROJ_N, dt_W + (size_t)i * D_INNER * DT_RANK,
            dt_b + (size_t)i * D_INNER, nullptr, dlt, D_INNER, D_INNER, DT_RANK);

        // selective scan (fused: + u*D, * silu(res))
        scan_kernel<<<(D_INNER * D_STATE) / 256, 256>>>(
            xc, dlt, A_log + (size_t)i * D_INNER * D_STATE,
            xdbl + DT_RANK, xdbl + DT_RANK + D_STATE, XPROJ_N,
            Dp + (size_t)i * D_INNER, xr + D_INNER, 2 * D_INNER, y);

        // x = x + y @ out_W[i]^T   [2048, 1024]
        mma_gemm<2><<<dim3(SEQLEN / 128, N_EMBD / 128), 256, GEMM_SMEM>>>(
            y, D_INNER, out_W + (size_t)i * N_EMBD * D_INNER,
            nullptr, x, x, N_EMBD, N_EMBD, D_INNER);
    }

    // final norm + tied LM head
    rmsnorm_kernel<<<SEQLEN, 256>>>(x, normf_w, normf_b, h);
    mma_gemm<0><<<dim3(SEQLEN / 128, (VOCAB + 127) / 128), 256, GEMM_SMEM>>>(
        h, N_EMBD, emb_W, nullptr, nullptr, out, VOCAB, VOCAB, N_EMBD);
}